// round 9
// baseline (speedup 1.0000x reference)
#include <cuda_runtime.h>
#include <cuda_bf16.h>
#include <cuda_fp16.h>
#include <cstdint>

#define N_TOT   131072
#define E_DIM   128
#define QKV_DIM 384
#define OUT_DIM 768
#define NROWS   141   // 140 table rows + bias row (masked token)

// ---------------- device scratch ---------------------------------------------
__device__ float g_tab_qkv[NROWS * QKV_DIM];
__device__ float g_valA[QKV_DIM];
__device__ float g_valB[QKV_DIM];
__device__ float g_bc[OUT_DIM];
__device__ float4 g_Spp[NROWS * NROWS];   // [ri*141+rj] -> 4 head scores (pre-scaled)
__device__ float4 g_SqA[NROWS];
__device__ float4 g_SqB[NROWS];
__device__ float4 g_SAk[NROWS];
__device__ float4 g_SBk[NROWS];
__device__ float4 g_c3[3];                // cAA, cAB, cBB
__device__ float g_vtab[NROWS * E_DIM];
__device__ __half g_Af[(size_t)N_TOT * E_DIM];
__device__ __half g_Bf[OUT_DIM * E_DIM];

#define SCALE 0.17677669529663687f  // 1/sqrt(32)

// ---------------- helpers ----------------------------------------------------
__device__ __forceinline__ uint32_t smem_u32(const void* p) {
    uint32_t a;
    asm("{ .reg .u64 t; cvta.to.shared.u64 t, %1; cvt.u32.u64 %0, t; }" : "=r"(a) : "l"(p));
    return a;
}
__device__ __forceinline__ void ldsm4(uint32_t& r0, uint32_t& r1, uint32_t& r2, uint32_t& r3,
                                      uint32_t addr) {
    asm volatile("ldmatrix.sync.aligned.m8n8.x4.shared.b16 {%0,%1,%2,%3}, [%4];"
                 : "=r"(r0), "=r"(r1), "=r"(r2), "=r"(r3) : "r"(addr));
}
__device__ __forceinline__ void mma16816(float* c, const uint32_t* a, const uint32_t* b) {
    asm volatile(
        "mma.sync.aligned.m16n8k16.row.col.f32.f16.f16.f32 "
        "{%0,%1,%2,%3}, {%4,%5,%6,%7}, {%8,%9}, {%0,%1,%2,%3};"
        : "+f"(c[0]), "+f"(c[1]), "+f"(c[2]), "+f"(c[3])
        : "r"(a[0]), "r"(a[1]), "r"(a[2]), "r"(a[3]), "r"(b[0]), "r"(b[1]));
}
__device__ __forceinline__ void cp16(uint32_t dst, const void* src) {
    asm volatile("cp.async.cg.shared.global [%0], [%1], 16;" :: "r"(dst), "l"(src));
}
__device__ __forceinline__ void cp_commit() {
    asm volatile("cp.async.commit_group;" ::: "memory");
}
template <int N>
__device__ __forceinline__ void cp_wait() {
    asm volatile("cp.async.wait_group %0;" :: "n"(N) : "memory");
}

// ---------------- P1: qkv rows for tables + bias row + valA/valB -------------
__global__ void precompute_qkv_kernel(
    const float* __restrict__ dev_t, const float* __restrict__ pse_t,
    const float* __restrict__ attr_t, const float* __restrict__ unit_t,
    const float* __restrict__ val_w, const float* __restrict__ val_b,
    const float* __restrict__ W, const float* __restrict__ b)
{
    __shared__ float emb[E_DIM];
    int blk = blockIdx.x;
    int j = threadIdx.x;

    const float* src = nullptr;
    float* dst;
    int has_bias = 1;
    if (blk < 10)        { src = dev_t  + blk * E_DIM;         dst = g_tab_qkv + blk * QKV_DIM; }
    else if (blk < 20)   { src = pse_t  + (blk - 10) * E_DIM;  dst = g_tab_qkv + blk * QKV_DIM; }
    else if (blk < 120)  { src = attr_t + (blk - 20) * E_DIM;  dst = g_tab_qkv + blk * QKV_DIM; }
    else if (blk < 140)  { src = unit_t + (blk - 120) * E_DIM; dst = g_tab_qkv + blk * QKV_DIM; }
    else if (blk == 140) { src = nullptr; dst = g_tab_qkv + 140 * QKV_DIM; }
    else if (blk == 141) { src = val_w; dst = g_valA; has_bias = 0; }
    else                 { src = val_b; dst = g_valB; }

    if (j < E_DIM) emb[j] = src ? src[j] : 0.0f;
    __syncthreads();

    const float4* Wr = (const float4*)(W + (size_t)j * E_DIM);
    const float4* em = (const float4*)emb;
    float acc = has_bias ? b[j] : 0.0f;
    #pragma unroll
    for (int e4 = 0; e4 < E_DIM / 4; e4++) {
        float4 w = Wr[e4];
        float4 v = em[e4];
        acc += w.x * v.x + w.y * v.y + w.z * v.z + w.w * v.w;
    }
    dst[j] = acc;
}

// ---------------- P2: Wc = out_w @ out_proj_w  (fp16) ------------------------
__global__ void precompute_wc_kernel(
    const float* __restrict__ out_w, const float* __restrict__ out_proj_w,
    const float* __restrict__ out_proj_b, const float* __restrict__ out_b)
{
    __shared__ float row[E_DIM];
    int o = blockIdx.x;
    int e = threadIdx.x;
    row[e] = out_w[(size_t)o * E_DIM + e];
    __syncthreads();

    float acc = 0.0f;
    #pragma unroll 8
    for (int m = 0; m < E_DIM; m++)
        acc += row[m] * out_proj_w[(size_t)m * E_DIM + e];

    g_Bf[(size_t)o * E_DIM + e] = __float2half(acc);

    if (e == 0) {
        float bb = out_b[o];
        for (int m = 0; m < E_DIM; m++) bb += row[m] * out_proj_b[m];
        g_bc[o] = bb;
    }
}

// ---------------- P3: pairwise score tables + v table ------------------------
__device__ __forceinline__ float dot32(const float* a, const float* b) {
    float s = 0.0f;
    #pragma unroll
    for (int d = 0; d < 32; d++) s += a[d] * b[d];
    return s;
}

__global__ void precompute_tables_kernel()
{
    __shared__ float q[E_DIM];
    int ri = blockIdx.x;
    int t = threadIdx.x;

    q[t] = g_tab_qkv[ri * QKV_DIM + t];
    g_vtab[ri * E_DIM + t] = g_tab_qkv[ri * QKV_DIM + 256 + t];
    __syncthreads();

    for (int rj = t; rj < NROWS; rj += 128) {
        const float* k = g_tab_qkv + rj * QKV_DIM + 128;
        float4 s;
        s.x = SCALE * dot32(q + 0,  k + 0);
        s.y = SCALE * dot32(q + 32, k + 32);
        s.z = SCALE * dot32(q + 64, k + 64);
        s.w = SCALE * dot32(q + 96, k + 96);
        g_Spp[ri * NROWS + rj] = s;
    }

    if (t < 4) {
        int h = t;
        ((float*)&g_SqA[ri])[h] = SCALE * dot32(q + 32 * h, g_valA + 128 + 32 * h);
        ((float*)&g_SqB[ri])[h] = SCALE * dot32(q + 32 * h, g_valB + 128 + 32 * h);
    } else if (t < 8) {
        int h = t - 4;
        const float* kr = g_tab_qkv + ri * QKV_DIM + 128 + 32 * h;
        ((float*)&g_SAk[ri])[h] = SCALE * dot32(g_valA + 32 * h, kr);
        ((float*)&g_SBk[ri])[h] = SCALE * dot32(g_valB + 32 * h, kr);
    }

    if (ri == 0 && t >= 8 && t < 12) {
        int h = t - 8;
        const float* Aq = g_valA + 32 * h;
        const float* Bq = g_valB + 32 * h;
        const float* Ak = g_valA + 128 + 32 * h;
        const float* Bk = g_valB + 128 + 32 * h;
        ((float*)&g_c3[0])[h] = SCALE * dot32(Aq, Ak);
        ((float*)&g_c3[1])[h] = SCALE * (dot32(Aq, Bk) + dot32(Bq, Ak));
        ((float*)&g_c3[2])[h] = SCALE * dot32(Bq, Bk);
    }
}

// ---------------- A: attention via tables, one warp per row ------------------
#define SMW 160
#define SC_OFF 0
#define WK_OFF 140

__global__ void __launch_bounds__(128) attn_kernel(
    const int* __restrict__ dev_ids, const int* __restrict__ pse_ids,
    const int* __restrict__ attr_ids, const int* __restrict__ unit_ids,
    const float* __restrict__ values, const int* __restrict__ mask)
{
    __shared__ float sm[4 * SMW];
    int w = threadIdx.x >> 5;
    int lane = threadIdx.x & 31;
    int n = blockIdx.x * 4 + w;
    float* S = sm + w * SMW;

    int mk0 = mask[n * 5 + 0];
    int mk1 = mask[n * 5 + 1];
    int mk2 = mask[n * 5 + 2];
    int mk3 = mask[n * 5 + 3];
    int mk4 = mask[n * 5 + 4];
    int r0 = mk0 ? dev_ids[n]        : 140;
    int r1 = mk1 ? 10 + pse_ids[n]   : 140;
    int r2 = mk2 ? 20 + attr_ids[n]  : 140;
    int r4 = mk4 ? 120 + unit_ids[n] : 140;
    float val = values[n];

    if (lane < 25) {
        int i = lane / 5;
        int j = lane - i * 5;
        int ri = (i == 0) ? r0 : (i == 1) ? r1 : (i == 2) ? r2 : (i == 3) ? 140 : r4;
        int rj = (j == 0) ? r0 : (j == 1) ? r1 : (j == 2) ? r2 : (j == 3) ? 140 : r4;
        float4 s;
        if (mk3 && (i == 3 || j == 3)) {
            if (i == 3 && j == 3) {
                float4 cAA = g_c3[0], cAB = g_c3[1], cBB = g_c3[2];
                float v2 = val * val;
                s.x = fmaf(v2, cAA.x, fmaf(val, cAB.x, cBB.x));
                s.y = fmaf(v2, cAA.y, fmaf(val, cAB.y, cBB.y));
                s.z = fmaf(v2, cAA.z, fmaf(val, cAB.z, cBB.z));
                s.w = fmaf(v2, cAA.w, fmaf(val, cAB.w, cBB.w));
            } else if (j == 3) {
                float4 a = g_SqA[ri], b = g_SqB[ri];
                s.x = fmaf(val, a.x, b.x);
                s.y = fmaf(val, a.y, b.y);
                s.z = fmaf(val, a.z, b.z);
                s.w = fmaf(val, a.w, b.w);
            } else {
                float4 a = g_SAk[rj], b = g_SBk[rj];
                s.x = fmaf(val, a.x, b.x);
                s.y = fmaf(val, a.y, b.y);
                s.z = fmaf(val, a.z, b.z);
                s.w = fmaf(val, a.w, b.w);
            }
        } else {
            s = g_Spp[ri * NROWS + rj];
        }
        S[SC_OFF + 0 * 25 + lane] = s.x;
        S[SC_OFF + 1 * 25 + lane] = s.y;
        S[SC_OFF + 2 * 25 + lane] = s.z;
        S[SC_OFF + 3 * 25 + lane] = s.w;
    }
    __syncwarp();

    // row stats + in-place normalized attn weights: lane (h,i) owns score row
    if (lane < 20) {
        int h = lane / 5;
        int i = lane - h * 5;
        float* sp = S + SC_OFF + h * 25 + i * 5;
        float s0 = sp[0], s1 = sp[1], s2 = sp[2], s3 = sp[3], s4 = sp[4];
        float m = fmaxf(fmaxf(fmaxf(s0, s1), fmaxf(s2, s3)), s4);
        float e0 = __expf(s0 - m), e1 = __expf(s1 - m), e2 = __expf(s2 - m);
        float e3 = __expf(s3 - m), e4 = __expf(s4 - m);
        float rs = 0.2f / (e0 + e1 + e2 + e3 + e4);   // includes mean 1/5
        sp[0] = e0 * rs; sp[1] = e1 * rs; sp[2] = e2 * rs;
        sp[3] = e3 * rs; sp[4] = e4 * rs;
    }
    __syncwarp();

    // column sums: wk[h][j] = sum_i attnw[h][i][j]
    if (lane < 20) {
        int h = lane / 5;
        int jj = lane - h * 5;
        const float* sp = S + SC_OFF + h * 25 + jj;
        S[WK_OFF + lane] = sp[0] + sp[5] + sp[10] + sp[15] + sp[20];
    }
    __syncwarp();

    // composed: each lane owns 4 consecutive e-dims (one head per lane)
    {
        int h = lane >> 3;
        float wk0 = S[WK_OFF + h * 5 + 0];
        float wk1 = S[WK_OFF + h * 5 + 1];
        float wk2 = S[WK_OFF + h * 5 + 2];
        float wk3 = S[WK_OFF + h * 5 + 3];
        float wk4 = S[WK_OFF + h * 5 + 4];

        float4 a0 = ((const float4*)(g_vtab + r0 * E_DIM))[lane];
        float4 a1 = ((const float4*)(g_vtab + r1 * E_DIM))[lane];
        float4 a2 = ((const float4*)(g_vtab + r2 * E_DIM))[lane];
        float4 a4 = ((const float4*)(g_vtab + r4 * E_DIM))[lane];
        float4 a3;
        if (mk3) {
            float4 vA = ((const float4*)(g_valA + 256))[lane];
            float4 vB = ((const float4*)(g_valB + 256))[lane];
            a3.x = fmaf(val, vA.x, vB.x);
            a3.y = fmaf(val, vA.y, vB.y);
            a3.z = fmaf(val, vA.z, vB.z);
            a3.w = fmaf(val, vA.w, vB.w);
        } else {
            a3 = ((const float4*)(g_vtab + 140 * E_DIM))[lane];
        }

        float cx = wk0 * a0.x + wk1 * a1.x + wk2 * a2.x + wk3 * a3.x + wk4 * a4.x;
        float cy = wk0 * a0.y + wk1 * a1.y + wk2 * a2.y + wk3 * a3.y + wk4 * a4.y;
        float cz = wk0 * a0.z + wk1 * a1.z + wk2 * a2.z + wk3 * a3.z + wk4 * a4.z;
        float cw = wk0 * a0.w + wk1 * a1.w + wk2 * a2.w + wk3 * a3.w + wk4 * a4.w;

        __half2 lo = __floats2half2_rn(cx, cy);
        __half2 hi = __floats2half2_rn(cz, cw);
        uint2 pack;
        pack.x = *(uint32_t*)&lo;
        pack.y = *(uint32_t*)&hi;
        *(uint2*)(g_Af + (size_t)n * E_DIM + lane * 4) = pack;
    }
}

// ---------------- G: fp16 MMA GEMM, 512 thr, 256m x 128n, A-resident ---------
#define GP 136
#define A_ROWS 256
#define SM_A_BYTES (A_ROWS * GP * 2)            // 69632
#define SM_B_BYTES (128 * GP * 2)               // 34816
#define SM_B_OFF(buf) (SM_A_BYTES + (buf) * SM_B_BYTES)
#define G_SMEM_BYTES (SM_A_BYTES + 2 * SM_B_BYTES)   // 139264

__device__ __forceinline__ void cp_tileA(uint32_t dst_base,
                                         const __half* __restrict__ src, int tid) {
    #pragma unroll
    for (int it = 0; it < 8; it++) {     // 256 rows x 16 chunks / 512 thr
        int idx = it * 512 + tid;
        int row = idx >> 4;
        int c8 = (idx & 15) << 3;
        cp16(dst_base + (row * GP + c8) * 2, src + row * E_DIM + c8);
    }
}
__device__ __forceinline__ void cp_tileB(uint32_t dst_base,
                                         const __half* __restrict__ src, int tid) {
    #pragma unroll
    for (int it = 0; it < 4; it++) {     // 128 rows x 16 chunks / 512 thr
        int idx = it * 512 + tid;
        int row = idx >> 4;
        int c8 = (idx & 15) << 3;
        cp16(dst_base + (row * GP + c8) * 2, src + row * E_DIM + c8);
    }
}

__global__ void __launch_bounds__(512, 1) gemm_mma_kernel(float* __restrict__ out)
{
    extern __shared__ char smem[];

    const int tid = threadIdx.x;
    const int wid = tid >> 5;
    const int lane = tid & 31;
    const int m0 = blockIdx.x * A_ROWS;

    const uint32_t aB = smem_u32(smem);
    const uint32_t bB0 = smem_u32(smem + SM_B_OFF(0));
    const uint32_t bB1 = smem_u32(smem + SM_B_OFF(1));

    // group0: A + B0 ; group1: B1
    cp_tileA(aB, g_Af + (size_t)m0 * E_DIM, tid);
    cp_tileB(bB0, g_Bf, tid);
    cp_commit();
    cp_tileB(bB1, g_Bf + (size_t)128 * E_DIM, tid);
    cp_commit();

    const int wm = (wid & 3) * 64;     // 4 m-groups of 64
    const int wn = (wid >> 2) * 32;    // 4 n-groups of 32

    const uint32_t aLane = aB + ((wm + (lane & 15)) * GP + ((lane >> 4) << 3)) * 2;
    const uint32_t bLaneOff = ((wn + (lane & 7) + ((lane & 16) >> 1)) * GP + (lane & 8)) * 2;

    const int mg = m0 + wm + (lane >> 2);
    const int ngb = wn + 2 * (lane & 3);

    cp_wait<1>();       // A + B0 resident
    __syncthreads();

    #pragma unroll 1
    for (int t = 0; t < 6; t++) {
        const uint32_t bLane = ((t & 1) ? bB1 : bB0) + bLaneOff;

        float c[4][4][4];
        #pragma unroll
        for (int mi = 0; mi < 4; mi++)
            #pragma unroll
            for (int ni = 0; ni < 4; ni++)
                #pragma unroll
                for (int q = 0; q < 4; q++) c[mi][ni][q] = 0.0f;

        #pragma unroll
        for (int ks = 0; ks < 8; ks++) {
            const uint32_t kOff = (uint32_t)(ks * 16 * 2);
            uint32_t a[4][4];
            #pragma unroll
            for (int mi = 0; mi < 4; mi++)
                ldsm4(a[mi][0], a[mi][1], a[mi][2], a[mi][3],
                      aLane + kOff + mi * (16 * GP * 2));
            uint32_t b[4][2];
            #pragma unroll
            for (int bj = 0; bj < 2; bj++)
                ldsm4(b[2 * bj][0], b[2 * bj][1], b[2 * bj + 1][0], b[2 * bj + 1][1],
                      bLane + kOff + bj * (16 * GP * 2));
            #pragma unroll
            for (int mi = 0; mi < 4; mi++)
                #pragma unroll
                for (int ni = 0; ni < 4; ni++)
                    mma16816(c[mi][ni], a[mi], b[ni]);
        }

        // epilogue for this n-tile
        const int colT = t * 128 + ngb;
        #pragma unroll
        for (int ni = 0; ni < 4; ni++) {
            int col = colT + ni * 8;
            float2 bc2 = *(const float2*)(g_bc + col);
            #pragma unroll
            for (int mi = 0; mi < 4; mi++) {
                int row = mg + mi * 16;
                float2 v0 = {c[mi][ni][0] + bc2.x, c[mi][ni][1] + bc2.y};
                float2 v1 = {c[mi][ni][2] + bc2.x, c[mi][ni][3] + bc2.y};
                *(float2*)(out + (size_t)row * OUT_DIM + col) = v0;
                *(float2*)(out + (size_t)(row + 8) * OUT_DIM + col) = v1;
            }
        }

        if (t == 5) break;
        __syncthreads();                 // all warps done reading buf t&1
        if (t < 4) {
            cp_tileB((t & 1) ? bB1 : bB0, g_Bf + (size_t)(t + 2) * 128 * E_DIM, tid);
            cp_commit();
            cp_wait<1>();                // B_{t+1} group complete
        } else {
            cp_wait<0>();                // drain B5
        }
        __syncthreads();
    }
}

// ---------------- launch -----------------------------------------------------
extern "C" void kernel_launch(void* const* d_in, const int* in_sizes, int n_in,
                              void* d_out, int out_size)
{
    const int*   device_ids = (const int*)d_in[0];
    const int*   pseudo_ids = (const int*)d_in[1];
    const int*   attr_ids   = (const int*)d_in[2];
    const int*   unit_ids   = (const int*)d_in[3];
    const float* values     = (const float*)d_in[4];
    const int*   mask       = (const int*)d_in[5];
    const float* dev_table  = (const float*)d_in[6];
    const float* pse_table  = (const float*)d_in[7];
    const float* attr_table = (const float*)d_in[8];
    const float* unit_table = (const float*)d_in[9];
    const float* val_w      = (const float*)d_in[10];
    const float* val_b      = (const float*)d_in[11];
    const float* in_proj_w  = (const float*)d_in[12];
    const float* in_proj_b  = (const float*)d_in[13];
    const float* out_proj_w = (const float*)d_in[14];
    const float* out_proj_b = (const float*)d_in[15];
    const float* out_w      = (const float*)d_in[16];
    const float* out_b      = (const float*)d_in[17];
    float* out = (float*)d_out;

    precompute_qkv_kernel<<<143, 384>>>(dev_table, pse_table, attr_table, unit_table,
                                        val_w, val_b, in_proj_w, in_proj_b);
    precompute_wc_kernel<<<768, 128>>>(out_w, out_proj_w, out_proj_b, out_b);
    precompute_tables_kernel<<<NROWS, 128>>>();

    attn_kernel<<<N_TOT / 4, 128>>>(device_ids, pseudo_ids, attr_ids, unit_ids,
                                    values, mask);

    cudaFuncSetAttribute(gemm_mma_kernel, cudaFuncAttributeMaxDynamicSharedMemorySize,
                         G_SMEM_BYTES);
    gemm_mma_kernel<<<N_TOT / A_ROWS, 512, G_SMEM_BYTES>>>(out);
}

// round 10
// speedup vs baseline: 1.0868x; 1.0868x over previous
#include <cuda_runtime.h>
#include <cuda_bf16.h>
#include <cuda_fp16.h>
#include <cstdint>

#define N_TOT   131072
#define E_DIM   128
#define QKV_DIM 384
#define OUT_DIM 768
#define NROWS   141   // 140 table rows + bias row (masked token)

// ---------------- device scratch ---------------------------------------------
__device__ float g_tab_qkv[NROWS * QKV_DIM];
__device__ float g_valA[QKV_DIM];
__device__ float g_valB[QKV_DIM];
__device__ float g_bc[OUT_DIM];
__device__ float4 g_Spp[NROWS * NROWS];   // [ri*141+rj] -> 4 head scores (pre-scaled)
__device__ float4 g_SqA[NROWS];
__device__ float4 g_SqB[NROWS];
__device__ float4 g_SAk[NROWS];
__device__ float4 g_SBk[NROWS];
__device__ float4 g_c3[3];                // cAA, cAB, cBB
__device__ float g_vtab[NROWS * E_DIM];
__device__ __half g_Af[(size_t)N_TOT * E_DIM];
__device__ __half g_Bf[OUT_DIM * E_DIM];

#define SCALE 0.17677669529663687f  // 1/sqrt(32)

// ---------------- helpers ----------------------------------------------------
__device__ __forceinline__ uint32_t smem_u32(const void* p) {
    uint32_t a;
    asm("{ .reg .u64 t; cvta.to.shared.u64 t, %1; cvt.u32.u64 %0, t; }" : "=r"(a) : "l"(p));
    return a;
}
__device__ __forceinline__ void ldsm4(uint32_t& r0, uint32_t& r1, uint32_t& r2, uint32_t& r3,
                                      uint32_t addr) {
    asm volatile("ldmatrix.sync.aligned.m8n8.x4.shared.b16 {%0,%1,%2,%3}, [%4];"
                 : "=r"(r0), "=r"(r1), "=r"(r2), "=r"(r3) : "r"(addr));
}
__device__ __forceinline__ void mma16816(float* c, const uint32_t* a, const uint32_t* b) {
    asm volatile(
        "mma.sync.aligned.m16n8k16.row.col.f32.f16.f16.f32 "
        "{%0,%1,%2,%3}, {%4,%5,%6,%7}, {%8,%9}, {%0,%1,%2,%3};"
        : "+f"(c[0]), "+f"(c[1]), "+f"(c[2]), "+f"(c[3])
        : "r"(a[0]), "r"(a[1]), "r"(a[2]), "r"(a[3]), "r"(b[0]), "r"(b[1]));
}
__device__ __forceinline__ void cp16(uint32_t dst, const void* src) {
    asm volatile("cp.async.cg.shared.global [%0], [%1], 16;" :: "r"(dst), "l"(src));
}
__device__ __forceinline__ void cp_commit() {
    asm volatile("cp.async.commit_group;" ::: "memory");
}
template <int N>
__device__ __forceinline__ void cp_wait() {
    asm volatile("cp.async.wait_group %0;" :: "n"(N) : "memory");
}

// ---------------- P1: qkv rows for tables + bias row + valA/valB -------------
__global__ void precompute_qkv_kernel(
    const float* __restrict__ dev_t, const float* __restrict__ pse_t,
    const float* __restrict__ attr_t, const float* __restrict__ unit_t,
    const float* __restrict__ val_w, const float* __restrict__ val_b,
    const float* __restrict__ W, const float* __restrict__ b)
{
    __shared__ float emb[E_DIM];
    int blk = blockIdx.x;
    int j = threadIdx.x;

    const float* src = nullptr;
    float* dst;
    int has_bias = 1;
    if (blk < 10)        { src = dev_t  + blk * E_DIM;         dst = g_tab_qkv + blk * QKV_DIM; }
    else if (blk < 20)   { src = pse_t  + (blk - 10) * E_DIM;  dst = g_tab_qkv + blk * QKV_DIM; }
    else if (blk < 120)  { src = attr_t + (blk - 20) * E_DIM;  dst = g_tab_qkv + blk * QKV_DIM; }
    else if (blk < 140)  { src = unit_t + (blk - 120) * E_DIM; dst = g_tab_qkv + blk * QKV_DIM; }
    else if (blk == 140) { src = nullptr; dst = g_tab_qkv + 140 * QKV_DIM; }
    else if (blk == 141) { src = val_w; dst = g_valA; has_bias = 0; }
    else                 { src = val_b; dst = g_valB; }

    if (j < E_DIM) emb[j] = src ? src[j] : 0.0f;
    __syncthreads();

    const float4* Wr = (const float4*)(W + (size_t)j * E_DIM);
    const float4* em = (const float4*)emb;
    float acc = has_bias ? b[j] : 0.0f;
    #pragma unroll
    for (int e4 = 0; e4 < E_DIM / 4; e4++) {
        float4 w = Wr[e4];
        float4 v = em[e4];
        acc += w.x * v.x + w.y * v.y + w.z * v.z + w.w * v.w;
    }
    dst[j] = acc;
}

// ---------------- P2: Wc = out_w @ out_proj_w  (fp16) ------------------------
__global__ void precompute_wc_kernel(
    const float* __restrict__ out_w, const float* __restrict__ out_proj_w,
    const float* __restrict__ out_proj_b, const float* __restrict__ out_b)
{
    __shared__ float row[E_DIM];
    int o = blockIdx.x;
    int e = threadIdx.x;
    row[e] = out_w[(size_t)o * E_DIM + e];
    __syncthreads();

    float acc = 0.0f;
    #pragma unroll 8
    for (int m = 0; m < E_DIM; m++)
        acc += row[m] * out_proj_w[(size_t)m * E_DIM + e];

    g_Bf[(size_t)o * E_DIM + e] = __float2half(acc);

    if (e == 0) {
        float bb = out_b[o];
        for (int m = 0; m < E_DIM; m++) bb += row[m] * out_proj_b[m];
        g_bc[o] = bb;
    }
}

// ---------------- P3: pairwise score tables + v table ------------------------
__device__ __forceinline__ float dot32(const float* a, const float* b) {
    float s = 0.0f;
    #pragma unroll
    for (int d = 0; d < 32; d++) s += a[d] * b[d];
    return s;
}

__global__ void precompute_tables_kernel()
{
    __shared__ float q[E_DIM];
    int ri = blockIdx.x;
    int t = threadIdx.x;

    q[t] = g_tab_qkv[ri * QKV_DIM + t];
    g_vtab[ri * E_DIM + t] = g_tab_qkv[ri * QKV_DIM + 256 + t];
    __syncthreads();

    for (int rj = t; rj < NROWS; rj += 128) {
        const float* k = g_tab_qkv + rj * QKV_DIM + 128;
        float4 s;
        s.x = SCALE * dot32(q + 0,  k + 0);
        s.y = SCALE * dot32(q + 32, k + 32);
        s.z = SCALE * dot32(q + 64, k + 64);
        s.w = SCALE * dot32(q + 96, k + 96);
        g_Spp[ri * NROWS + rj] = s;
    }

    if (t < 4) {
        int h = t;
        ((float*)&g_SqA[ri])[h] = SCALE * dot32(q + 32 * h, g_valA + 128 + 32 * h);
        ((float*)&g_SqB[ri])[h] = SCALE * dot32(q + 32 * h, g_valB + 128 + 32 * h);
    } else if (t < 8) {
        int h = t - 4;
        const float* kr = g_tab_qkv + ri * QKV_DIM + 128 + 32 * h;
        ((float*)&g_SAk[ri])[h] = SCALE * dot32(g_valA + 32 * h, kr);
        ((float*)&g_SBk[ri])[h] = SCALE * dot32(g_valB + 32 * h, kr);
    }

    if (ri == 0 && t >= 8 && t < 12) {
        int h = t - 8;
        const float* Aq = g_valA + 32 * h;
        const float* Bq = g_valB + 32 * h;
        const float* Ak = g_valA + 128 + 32 * h;
        const float* Bk = g_valB + 128 + 32 * h;
        ((float*)&g_c3[0])[h] = SCALE * dot32(Aq, Ak);
        ((float*)&g_c3[1])[h] = SCALE * (dot32(Aq, Bk) + dot32(Bq, Ak));
        ((float*)&g_c3[2])[h] = SCALE * dot32(Bq, Bk);
    }
}

// ---------------- A: attention via tables, one warp per row ------------------
#define SMW 160
#define SC_OFF 0
#define WK_OFF 140

__global__ void __launch_bounds__(128) attn_kernel(
    const int* __restrict__ dev_ids, const int* __restrict__ pse_ids,
    const int* __restrict__ attr_ids, const int* __restrict__ unit_ids,
    const float* __restrict__ values, const int* __restrict__ mask)
{
    __shared__ float sm[4 * SMW];
    int w = threadIdx.x >> 5;
    int lane = threadIdx.x & 31;
    int n = blockIdx.x * 4 + w;
    float* S = sm + w * SMW;

    int mk0 = mask[n * 5 + 0];
    int mk1 = mask[n * 5 + 1];
    int mk2 = mask[n * 5 + 2];
    int mk3 = mask[n * 5 + 3];
    int mk4 = mask[n * 5 + 4];
    int r0 = mk0 ? dev_ids[n]        : 140;
    int r1 = mk1 ? 10 + pse_ids[n]   : 140;
    int r2 = mk2 ? 20 + attr_ids[n]  : 140;
    int r4 = mk4 ? 120 + unit_ids[n] : 140;
    float val = values[n];

    if (lane < 25) {
        int i = lane / 5;
        int j = lane - i * 5;
        int ri = (i == 0) ? r0 : (i == 1) ? r1 : (i == 2) ? r2 : (i == 3) ? 140 : r4;
        int rj = (j == 0) ? r0 : (j == 1) ? r1 : (j == 2) ? r2 : (j == 3) ? 140 : r4;
        float4 s;
        if (mk3 && (i == 3 || j == 3)) {
            if (i == 3 && j == 3) {
                float4 cAA = g_c3[0], cAB = g_c3[1], cBB = g_c3[2];
                float v2 = val * val;
                s.x = fmaf(v2, cAA.x, fmaf(val, cAB.x, cBB.x));
                s.y = fmaf(v2, cAA.y, fmaf(val, cAB.y, cBB.y));
                s.z = fmaf(v2, cAA.z, fmaf(val, cAB.z, cBB.z));
                s.w = fmaf(v2, cAA.w, fmaf(val, cAB.w, cBB.w));
            } else if (j == 3) {
                float4 a = g_SqA[ri], b = g_SqB[ri];
                s.x = fmaf(val, a.x, b.x);
                s.y = fmaf(val, a.y, b.y);
                s.z = fmaf(val, a.z, b.z);
                s.w = fmaf(val, a.w, b.w);
            } else {
                float4 a = g_SAk[rj], b = g_SBk[rj];
                s.x = fmaf(val, a.x, b.x);
                s.y = fmaf(val, a.y, b.y);
                s.z = fmaf(val, a.z, b.z);
                s.w = fmaf(val, a.w, b.w);
            }
        } else {
            s = g_Spp[ri * NROWS + rj];
        }
        S[SC_OFF + 0 * 25 + lane] = s.x;
        S[SC_OFF + 1 * 25 + lane] = s.y;
        S[SC_OFF + 2 * 25 + lane] = s.z;
        S[SC_OFF + 3 * 25 + lane] = s.w;
    }
    __syncwarp();

    // row stats + in-place normalized attn weights
    if (lane < 20) {
        int h = lane / 5;
        int i = lane - h * 5;
        float* sp = S + SC_OFF + h * 25 + i * 5;
        float s0 = sp[0], s1 = sp[1], s2 = sp[2], s3 = sp[3], s4 = sp[4];
        float m = fmaxf(fmaxf(fmaxf(s0, s1), fmaxf(s2, s3)), s4);
        float e0 = __expf(s0 - m), e1 = __expf(s1 - m), e2 = __expf(s2 - m);
        float e3 = __expf(s3 - m), e4 = __expf(s4 - m);
        float rs = 0.2f / (e0 + e1 + e2 + e3 + e4);
        sp[0] = e0 * rs; sp[1] = e1 * rs; sp[2] = e2 * rs;
        sp[3] = e3 * rs; sp[4] = e4 * rs;
    }
    __syncwarp();

    if (lane < 20) {
        int h = lane / 5;
        int jj = lane - h * 5;
        const float* sp = S + SC_OFF + h * 25 + jj;
        S[WK_OFF + lane] = sp[0] + sp[5] + sp[10] + sp[15] + sp[20];
    }
    __syncwarp();

    // composed: each lane owns 4 consecutive e-dims
    {
        int h = lane >> 3;
        float wk0 = S[WK_OFF + h * 5 + 0];
        float wk1 = S[WK_OFF + h * 5 + 1];
        float wk2 = S[WK_OFF + h * 5 + 2];
        float wk3 = S[WK_OFF + h * 5 + 3];
        float wk4 = S[WK_OFF + h * 5 + 4];

        float4 a0 = ((const float4*)(g_vtab + r0 * E_DIM))[lane];
        float4 a1 = ((const float4*)(g_vtab + r1 * E_DIM))[lane];
        float4 a2 = ((const float4*)(g_vtab + r2 * E_DIM))[lane];
        float4 a4 = ((const float4*)(g_vtab + r4 * E_DIM))[lane];
        float4 a3;
        if (mk3) {
            float4 vA = ((const float4*)(g_valA + 256))[lane];
            float4 vB = ((const float4*)(g_valB + 256))[lane];
            a3.x = fmaf(val, vA.x, vB.x);
            a3.y = fmaf(val, vA.y, vB.y);
            a3.z = fmaf(val, vA.z, vB.z);
            a3.w = fmaf(val, vA.w, vB.w);
        } else {
            a3 = ((const float4*)(g_vtab + 140 * E_DIM))[lane];
        }

        float cx = wk0 * a0.x + wk1 * a1.x + wk2 * a2.x + wk3 * a3.x + wk4 * a4.x;
        float cy = wk0 * a0.y + wk1 * a1.y + wk2 * a2.y + wk3 * a3.y + wk4 * a4.y;
        float cz = wk0 * a0.z + wk1 * a1.z + wk2 * a2.z + wk3 * a3.z + wk4 * a4.z;
        float cw = wk0 * a0.w + wk1 * a1.w + wk2 * a2.w + wk3 * a3.w + wk4 * a4.w;

        __half2 lo = __floats2half2_rn(cx, cy);
        __half2 hi = __floats2half2_rn(cz, cw);
        uint2 pack;
        pack.x = *(uint32_t*)&lo;
        pack.y = *(uint32_t*)&hi;
        *(uint2*)(g_Af + (size_t)n * E_DIM + lane * 4) = pack;
    }
}

// ---------------- G: fp16 MMA GEMM, 128m x 64n, 4 CTAs/SM (occ 50%) ----------
#define GP 136
#define SM_A_BYTES (128 * GP * 2)   // 34816
#define SM_B_BYTES (64 * GP * 2)    // 17408
#define G_SMEM_BYTES (SM_A_BYTES + SM_B_BYTES)   // 52224

__global__ void __launch_bounds__(256, 4) gemm_mma_kernel(float* __restrict__ out)
{
    extern __shared__ char smem[];

    const int tid = threadIdx.x;
    const int wid = tid >> 5;
    const int lane = tid & 31;
    const int n0 = blockIdx.x * 64;
    const int m0 = blockIdx.y * 128;

    const uint32_t aB = smem_u32(smem);
    const uint32_t bB = smem_u32(smem + SM_A_BYTES);

    // prologue: A (128 rows) + B (64 rows), one cp.async group
    #pragma unroll
    for (int it = 0; it < 8; it++) {       // A: 2048 chunks / 256 thr
        int idx = it * 256 + tid;
        int row = idx >> 4;
        int c8 = (idx & 15) << 3;
        cp16(aB + (row * GP + c8) * 2, g_Af + (size_t)(m0 + row) * E_DIM + c8);
    }
    #pragma unroll
    for (int it = 0; it < 4; it++) {       // B: 1024 chunks / 256 thr
        int idx = it * 256 + tid;
        int row = idx >> 4;
        int c8 = (idx & 15) << 3;
        cp16(bB + (row * GP + c8) * 2, g_Bf + (size_t)(n0 + row) * E_DIM + c8);
    }
    cp_commit();

    const int wm = (wid & 3) * 32;     // 4 m-groups of 32
    const int wn = (wid >> 2) * 32;    // 2 n-groups of 32

    const uint32_t aLane = aB + ((wm + (lane & 15)) * GP + ((lane >> 4) << 3)) * 2;
    const uint32_t bLane = bB + ((wn + (lane & 7) + ((lane & 16) >> 1)) * GP + (lane & 8)) * 2;

    float c[2][4][4];
    #pragma unroll
    for (int mi = 0; mi < 2; mi++)
        #pragma unroll
        for (int ni = 0; ni < 4; ni++)
            #pragma unroll
            for (int q = 0; q < 4; q++) c[mi][ni][q] = 0.0f;

    cp_wait<0>();
    __syncthreads();

    #pragma unroll
    for (int ks = 0; ks < 8; ks++) {
        const uint32_t kOff = (uint32_t)(ks * 16 * 2);
        uint32_t a[2][4];
        #pragma unroll
        for (int mi = 0; mi < 2; mi++)
            ldsm4(a[mi][0], a[mi][1], a[mi][2], a[mi][3],
                  aLane + kOff + mi * (16 * GP * 2));
        uint32_t b[4][2];
        #pragma unroll
        for (int bj = 0; bj < 2; bj++)
            ldsm4(b[2 * bj][0], b[2 * bj][1], b[2 * bj + 1][0], b[2 * bj + 1][1],
                  bLane + kOff + bj * (16 * GP * 2));
        #pragma unroll
        for (int mi = 0; mi < 2; mi++)
            #pragma unroll
            for (int ni = 0; ni < 4; ni++)
                mma16816(c[mi][ni], a[mi], b[ni]);
    }

    // epilogue: +bc, streaming stores (don't pollute L2)
    const int mg = m0 + wm + (lane >> 2);
    const int ngb = n0 + wn + 2 * (lane & 3);
    #pragma unroll
    for (int ni = 0; ni < 4; ni++) {
        int col = ngb + ni * 8;
        float2 bc2 = *(const float2*)(g_bc + col);
        #pragma unroll
        for (int mi = 0; mi < 2; mi++) {
            int row = mg + mi * 16;
            float2 v0 = {c[mi][ni][0] + bc2.x, c[mi][ni][1] + bc2.y};
            float2 v1 = {c[mi][ni][2] + bc2.x, c[mi][ni][3] + bc2.y};
            __stcs((float2*)(out + (size_t)row * OUT_DIM + col), v0);
            __stcs((float2*)(out + (size_t)(row + 8) * OUT_DIM + col), v1);
        }
    }
}

// ---------------- launch -----------------------------------------------------
extern "C" void kernel_launch(void* const* d_in, const int* in_sizes, int n_in,
                              void* d_out, int out_size)
{
    const int*   device_ids = (const int*)d_in[0];
    const int*   pseudo_ids = (const int*)d_in[1];
    const int*   attr_ids   = (const int*)d_in[2];
    const int*   unit_ids   = (const int*)d_in[3];
    const float* values     = (const float*)d_in[4];
    const int*   mask       = (const int*)d_in[5];
    const float* dev_table  = (const float*)d_in[6];
    const float* pse_table  = (const float*)d_in[7];
    const float* attr_table = (const float*)d_in[8];
    const float* unit_table = (const float*)d_in[9];
    const float* val_w      = (const float*)d_in[10];
    const float* val_b      = (const float*)d_in[11];
    const float* in_proj_w  = (const float*)d_in[12];
    const float* in_proj_b  = (const float*)d_in[13];
    const float* out_proj_w = (const float*)d_in[14];
    const float* out_proj_b = (const float*)d_in[15];
    const float* out_w      = (const float*)d_in[16];
    const float* out_b      = (const float*)d_in[17];
    float* out = (float*)d_out;

    precompute_qkv_kernel<<<143, 384>>>(dev_table, pse_table, attr_table, unit_table,
                                        val_w, val_b, in_proj_w, in_proj_b);
    precompute_wc_kernel<<<768, 128>>>(out_w, out_proj_w, out_proj_b, out_b);
    precompute_tables_kernel<<<NROWS, 128>>>();

    attn_kernel<<<N_TOT / 4, 128>>>(device_ids, pseudo_ids, attr_ids, unit_ids,
                                    values, mask);

    cudaFuncSetAttribute(gemm_mma_kernel, cudaFuncAttributeMaxDynamicSharedMemorySize,
                         G_SMEM_BYTES);
    gemm_mma_kernel<<<dim3(OUT_DIM / 64, N_TOT / 128), 256, G_SMEM_BYTES>>>(out);
}

// round 11
// speedup vs baseline: 1.2597x; 1.1590x over previous
#include <cuda_runtime.h>
#include <cuda_bf16.h>
#include <cuda_fp16.h>
#include <cstdint>

#define N_TOT   131072
#define E_DIM   128
#define QKV_DIM 384
#define OUT_DIM 768
#define NROWS   141   // 140 table rows + bias row (masked token)

// ---------------- device scratch ---------------------------------------------
__device__ float g_tab_qkv[NROWS * QKV_DIM];
__device__ float g_valA[QKV_DIM];
__device__ float g_valB[QKV_DIM];
__device__ float g_bc[OUT_DIM];
__device__ float4 g_Spp[NROWS * NROWS];   // [ri*141+rj] -> 4 head scores (pre-scaled)
__device__ float4 g_SqA[NROWS];
__device__ float4 g_SqB[NROWS];
__device__ float4 g_SAk[NROWS];
__device__ float4 g_SBk[NROWS];
__device__ float4 g_c3[3];                // cAA, cAB, cBB
__device__ float g_vtab[NROWS * E_DIM];
__device__ __half g_Af[(size_t)N_TOT * E_DIM];
__device__ __half g_Bf[OUT_DIM * E_DIM];  // rows stored in PHYSICAL (permuted) order

#define SCALE 0.17677669529663687f  // 1/sqrt(32)

// ---------------- helpers ----------------------------------------------------
__device__ __forceinline__ uint32_t smem_u32(const void* p) {
    uint32_t a;
    asm("{ .reg .u64 t; cvta.to.shared.u64 t, %1; cvt.u32.u64 %0, t; }" : "=r"(a) : "l"(p));
    return a;
}
__device__ __forceinline__ void ldsm4(uint32_t& r0, uint32_t& r1, uint32_t& r2, uint32_t& r3,
                                      uint32_t addr) {
    asm volatile("ldmatrix.sync.aligned.m8n8.x4.shared.b16 {%0,%1,%2,%3}, [%4];"
                 : "=r"(r0), "=r"(r1), "=r"(r2), "=r"(r3) : "r"(addr));
}
__device__ __forceinline__ void mma16816(float* c, const uint32_t* a, const uint32_t* b) {
    asm volatile(
        "mma.sync.aligned.m16n8k16.row.col.f32.f16.f16.f32 "
        "{%0,%1,%2,%3}, {%4,%5,%6,%7}, {%8,%9}, {%0,%1,%2,%3};"
        : "+f"(c[0]), "+f"(c[1]), "+f"(c[2]), "+f"(c[3])
        : "r"(a[0]), "r"(a[1]), "r"(a[2]), "r"(a[3]), "r"(b[0]), "r"(b[1]));
}
__device__ __forceinline__ void cp16(uint32_t dst, const void* src) {
    asm volatile("cp.async.cg.shared.global [%0], [%1], 16;" :: "r"(dst), "l"(src));
}
__device__ __forceinline__ void cp_commit() {
    asm volatile("cp.async.commit_group;" ::: "memory");
}
template <int N>
__device__ __forceinline__ void cp_wait() {
    asm volatile("cp.async.wait_group %0;" :: "n"(N) : "memory");
}

// ---------------- P1: qkv rows for tables + bias row + valA/valB -------------
__global__ void precompute_qkv_kernel(
    const float* __restrict__ dev_t, const float* __restrict__ pse_t,
    const float* __restrict__ attr_t, const float* __restrict__ unit_t,
    const float* __restrict__ val_w, const float* __restrict__ val_b,
    const float* __restrict__ W, const float* __restrict__ b)
{
    __shared__ float emb[E_DIM];
    int blk = blockIdx.x;
    int j = threadIdx.x;

    const float* src = nullptr;
    float* dst;
    int has_bias = 1;
    if (blk < 10)        { src = dev_t  + blk * E_DIM;         dst = g_tab_qkv + blk * QKV_DIM; }
    else if (blk < 20)   { src = pse_t  + (blk - 10) * E_DIM;  dst = g_tab_qkv + blk * QKV_DIM; }
    else if (blk < 120)  { src = attr_t + (blk - 20) * E_DIM;  dst = g_tab_qkv + blk * QKV_DIM; }
    else if (blk < 140)  { src = unit_t + (blk - 120) * E_DIM; dst = g_tab_qkv + blk * QKV_DIM; }
    else if (blk == 140) { src = nullptr; dst = g_tab_qkv + 140 * QKV_DIM; }
    else if (blk == 141) { src = val_w; dst = g_valA; has_bias = 0; }
    else                 { src = val_b; dst = g_valB; }

    if (j < E_DIM) emb[j] = src ? src[j] : 0.0f;
    __syncthreads();

    const float4* Wr = (const float4*)(W + (size_t)j * E_DIM);
    const float4* em = (const float4*)emb;
    float acc = has_bias ? b[j] : 0.0f;
    #pragma unroll
    for (int e4 = 0; e4 < E_DIM / 4; e4++) {
        float4 w = Wr[e4];
        float4 v = em[e4];
        acc += w.x * v.x + w.y * v.y + w.z * v.z + w.w * v.w;
    }
    dst[j] = acc;
}

// ---------------- P2: Wc = out_w @ out_proj_w  (fp16, PERMUTED rows) ---------
// logical col L = 16T + 4*tq + 2*i1 + j   lives at physical row
// phys = 16T + 8*i1 + 2*tq + j, so the MMA epilogue emits 4 consecutive
// logical columns per thread (STG.128).
__global__ void precompute_wc_kernel(
    const float* __restrict__ out_w, const float* __restrict__ out_proj_w,
    const float* __restrict__ out_proj_b, const float* __restrict__ out_b)
{
    __shared__ float row[E_DIM];
    int o = blockIdx.x;             // logical output column
    int e = threadIdx.x;
    row[e] = out_w[(size_t)o * E_DIM + e];
    __syncthreads();

    float acc = 0.0f;
    #pragma unroll 8
    for (int m = 0; m < E_DIM; m++)
        acc += row[m] * out_proj_w[(size_t)m * E_DIM + e];

    int T = o >> 4, r = o & 15;
    int tq = r >> 2, w = r & 3;
    int i1 = w >> 1, j = w & 1;
    int phys = (T << 4) + (i1 << 3) + (tq << 1) + j;
    g_Bf[(size_t)phys * E_DIM + e] = __float2half(acc);

    if (e == 0) {
        float bb = out_b[o];
        for (int m = 0; m < E_DIM; m++) bb += row[m] * out_proj_b[m];
        g_bc[o] = bb;               // bc stays in logical order
    }
}

// ---------------- P3: pairwise score tables + v table ------------------------
__device__ __forceinline__ float dot32(const float* a, const float* b) {
    float s = 0.0f;
    #pragma unroll
    for (int d = 0; d < 32; d++) s += a[d] * b[d];
    return s;
}

__global__ void precompute_tables_kernel()
{
    __shared__ float q[E_DIM];
    int ri = blockIdx.x;
    int t = threadIdx.x;

    q[t] = g_tab_qkv[ri * QKV_DIM + t];
    g_vtab[ri * E_DIM + t] = g_tab_qkv[ri * QKV_DIM + 256 + t];
    __syncthreads();

    for (int rj = t; rj < NROWS; rj += 128) {
        const float* k = g_tab_qkv + rj * QKV_DIM + 128;
        float4 s;
        s.x = SCALE * dot32(q + 0,  k + 0);
        s.y = SCALE * dot32(q + 32, k + 32);
        s.z = SCALE * dot32(q + 64, k + 64);
        s.w = SCALE * dot32(q + 96, k + 96);
        g_Spp[ri * NROWS + rj] = s;
    }

    if (t < 4) {
        int h = t;
        ((float*)&g_SqA[ri])[h] = SCALE * dot32(q + 32 * h, g_valA + 128 + 32 * h);
        ((float*)&g_SqB[ri])[h] = SCALE * dot32(q + 32 * h, g_valB + 128 + 32 * h);
    } else if (t < 8) {
        int h = t - 4;
        const float* kr = g_tab_qkv + ri * QKV_DIM + 128 + 32 * h;
        ((float*)&g_SAk[ri])[h] = SCALE * dot32(g_valA + 32 * h, kr);
        ((float*)&g_SBk[ri])[h] = SCALE * dot32(g_valB + 32 * h, kr);
    }

    if (ri == 0 && t >= 8 && t < 12) {
        int h = t - 8;
        const float* Aq = g_valA + 32 * h;
        const float* Bq = g_valB + 32 * h;
        const float* Ak = g_valA + 128 + 32 * h;
        const float* Bk = g_valB + 128 + 32 * h;
        ((float*)&g_c3[0])[h] = SCALE * dot32(Aq, Ak);
        ((float*)&g_c3[1])[h] = SCALE * (dot32(Aq, Bk) + dot32(Bq, Ak));
        ((float*)&g_c3[2])[h] = SCALE * dot32(Bq, Bk);
    }
}

// ---------------- A: attention via tables, one warp per row ------------------
#define SMW 160
#define SC_OFF 0
#define WK_OFF 140

__global__ void __launch_bounds__(128) attn_kernel(
    const int* __restrict__ dev_ids, const int* __restrict__ pse_ids,
    const int* __restrict__ attr_ids, const int* __restrict__ unit_ids,
    const float* __restrict__ values, const int* __restrict__ mask)
{
    __shared__ float sm[4 * SMW];
    int w = threadIdx.x >> 5;
    int lane = threadIdx.x & 31;
    int n = blockIdx.x * 4 + w;
    float* S = sm + w * SMW;

    int mk0 = mask[n * 5 + 0];
    int mk1 = mask[n * 5 + 1];
    int mk2 = mask[n * 5 + 2];
    int mk3 = mask[n * 5 + 3];
    int mk4 = mask[n * 5 + 4];
    int r0 = mk0 ? dev_ids[n]        : 140;
    int r1 = mk1 ? 10 + pse_ids[n]   : 140;
    int r2 = mk2 ? 20 + attr_ids[n]  : 140;
    int r4 = mk4 ? 120 + unit_ids[n] : 140;
    float val = values[n];

    if (lane < 25) {
        int i = lane / 5;
        int j = lane - i * 5;
        int ri = (i == 0) ? r0 : (i == 1) ? r1 : (i == 2) ? r2 : (i == 3) ? 140 : r4;
        int rj = (j == 0) ? r0 : (j == 1) ? r1 : (j == 2) ? r2 : (j == 3) ? 140 : r4;
        float4 s;
        if (mk3 && (i == 3 || j == 3)) {
            if (i == 3 && j == 3) {
                float4 cAA = g_c3[0], cAB = g_c3[1], cBB = g_c3[2];
                float v2 = val * val;
                s.x = fmaf(v2, cAA.x, fmaf(val, cAB.x, cBB.x));
                s.y = fmaf(v2, cAA.y, fmaf(val, cAB.y, cBB.y));
                s.z = fmaf(v2, cAA.z, fmaf(val, cAB.z, cBB.z));
                s.w = fmaf(v2, cAA.w, fmaf(val, cAB.w, cBB.w));
            } else if (j == 3) {
                float4 a = g_SqA[ri], b = g_SqB[ri];
                s.x = fmaf(val, a.x, b.x);
                s.y = fmaf(val, a.y, b.y);
                s.z = fmaf(val, a.z, b.z);
                s.w = fmaf(val, a.w, b.w);
            } else {
                float4 a = g_SAk[rj], b = g_SBk[rj];
                s.x = fmaf(val, a.x, b.x);
                s.y = fmaf(val, a.y, b.y);
                s.z = fmaf(val, a.z, b.z);
                s.w = fmaf(val, a.w, b.w);
            }
        } else {
            s = g_Spp[ri * NROWS + rj];
        }
        S[SC_OFF + 0 * 25 + lane] = s.x;
        S[SC_OFF + 1 * 25 + lane] = s.y;
        S[SC_OFF + 2 * 25 + lane] = s.z;
        S[SC_OFF + 3 * 25 + lane] = s.w;
    }
    __syncwarp();

    // row stats + in-place normalized attn weights
    if (lane < 20) {
        int h = lane / 5;
        int i = lane - h * 5;
        float* sp = S + SC_OFF + h * 25 + i * 5;
        float s0 = sp[0], s1 = sp[1], s2 = sp[2], s3 = sp[3], s4 = sp[4];
        float m = fmaxf(fmaxf(fmaxf(s0, s1), fmaxf(s2, s3)), s4);
        float e0 = __expf(s0 - m), e1 = __expf(s1 - m), e2 = __expf(s2 - m);
        float e3 = __expf(s3 - m), e4 = __expf(s4 - m);
        float rs = 0.2f / (e0 + e1 + e2 + e3 + e4);
        sp[0] = e0 * rs; sp[1] = e1 * rs; sp[2] = e2 * rs;
        sp[3] = e3 * rs; sp[4] = e4 * rs;
    }
    __syncwarp();

    if (lane < 20) {
        int h = lane / 5;
        int jj = lane - h * 5;
        const float* sp = S + SC_OFF + h * 25 + jj;
        S[WK_OFF + lane] = sp[0] + sp[5] + sp[10] + sp[15] + sp[20];
    }
    __syncwarp();

    // composed: each lane owns 4 consecutive e-dims
    {
        int h = lane >> 3;
        float wk0 = S[WK_OFF + h * 5 + 0];
        float wk1 = S[WK_OFF + h * 5 + 1];
        float wk2 = S[WK_OFF + h * 5 + 2];
        float wk3 = S[WK_OFF + h * 5 + 3];
        float wk4 = S[WK_OFF + h * 5 + 4];

        float4 a0 = ((const float4*)(g_vtab + r0 * E_DIM))[lane];
        float4 a1 = ((const float4*)(g_vtab + r1 * E_DIM))[lane];
        float4 a2 = ((const float4*)(g_vtab + r2 * E_DIM))[lane];
        float4 a4 = ((const float4*)(g_vtab + r4 * E_DIM))[lane];
        float4 a3;
        if (mk3) {
            float4 vA = ((const float4*)(g_valA + 256))[lane];
            float4 vB = ((const float4*)(g_valB + 256))[lane];
            a3.x = fmaf(val, vA.x, vB.x);
            a3.y = fmaf(val, vA.y, vB.y);
            a3.z = fmaf(val, vA.z, vB.z);
            a3.w = fmaf(val, vA.w, vB.w);
        } else {
            a3 = ((const float4*)(g_vtab + 140 * E_DIM))[lane];
        }

        float cx = wk0 * a0.x + wk1 * a1.x + wk2 * a2.x + wk3 * a3.x + wk4 * a4.x;
        float cy = wk0 * a0.y + wk1 * a1.y + wk2 * a2.y + wk3 * a3.y + wk4 * a4.y;
        float cz = wk0 * a0.z + wk1 * a1.z + wk2 * a2.z + wk3 * a3.z + wk4 * a4.z;
        float cw = wk0 * a0.w + wk1 * a1.w + wk2 * a2.w + wk3 * a3.w + wk4 * a4.w;

        __half2 lo = __floats2half2_rn(cx, cy);
        __half2 hi = __floats2half2_rn(cz, cw);
        uint2 pack;
        pack.x = *(uint32_t*)&lo;
        pack.y = *(uint32_t*)&hi;
        *(uint2*)(g_Af + (size_t)n * E_DIM + lane * 4) = pack;
    }
}

// ---------------- G: fp16 MMA GEMM, A-resident, permuted STG.128 epilogue ----
// 1024 CTAs x 256 thr, 2 CTAs/SM. Each CTA: 128-row stripe x all 768 cols.
#define GP 136
#define TILE_HALF (128 * GP)
#define SM_A_OFF 0
#define SM_B_OFF(buf) ((1 + (buf)) * TILE_HALF * 2)
#define G_SMEM_BYTES (3 * TILE_HALF * 2)   // 104448 B

__device__ __forceinline__ void cp_tile128(uint32_t dst_base,
                                           const __half* __restrict__ src, int tid) {
    #pragma unroll
    for (int it = 0; it < 8; it++) {
        int idx = it * 256 + tid;
        int row = idx >> 4;
        int c8 = (idx & 15) << 3;
        cp16(dst_base + (row * GP + c8) * 2, src + row * E_DIM + c8);
    }
}

__global__ void __launch_bounds__(256, 2) gemm_mma_kernel(float* __restrict__ out)
{
    extern __shared__ char smem[];

    const int tid = threadIdx.x;
    const int wid = tid >> 5;
    const int lane = tid & 31;
    const int m0 = blockIdx.x * 128;

    const uint32_t aB = smem_u32(smem + SM_A_OFF);
    const uint32_t bB0 = smem_u32(smem + SM_B_OFF(0));
    const uint32_t bB1 = smem_u32(smem + SM_B_OFF(1));

    // group0: A + B0 ; group1: B1
    cp_tile128(aB, g_Af + (size_t)m0 * E_DIM, tid);
    cp_tile128(bB0, g_Bf, tid);
    cp_commit();
    cp_tile128(bB1, g_Bf + (size_t)128 * E_DIM, tid);
    cp_commit();

    const int wm = (wid & 1) * 64;     // 2 m-groups of 64
    const int wn = (wid >> 1) * 32;    // 4 n-groups of 32 (physical B rows)

    const uint32_t aLane = aB + ((wm + (lane & 15)) * GP + ((lane >> 4) << 3)) * 2;
    const uint32_t bLaneOff = ((wn + (lane & 7) + ((lane & 16) >> 1)) * GP + (lane & 8)) * 2;

    const int mg = m0 + wm + (lane >> 2);
    const int cq = wn + 4 * (lane & 3);   // logical col base for this thread

    cp_wait<1>();       // A + B0 resident
    __syncthreads();

    #pragma unroll 1
    for (int t = 0; t < 6; t++) {
        const uint32_t bLane = ((t & 1) ? bB1 : bB0) + bLaneOff;

        float c[4][4][4];
        #pragma unroll
        for (int mi = 0; mi < 4; mi++)
            #pragma unroll
            for (int ni = 0; ni < 4; ni++)
                #pragma unroll
                for (int q = 0; q < 4; q++) c[mi][ni][q] = 0.0f;

        #pragma unroll
        for (int ks = 0; ks < 8; ks++) {
            const uint32_t kOff = (uint32_t)(ks * 16 * 2);
            uint32_t a[4][4];
            #pragma unroll
            for (int mi = 0; mi < 4; mi++)
                ldsm4(a[mi][0], a[mi][1], a[mi][2], a[mi][3],
                      aLane + kOff + mi * (16 * GP * 2));
            uint32_t b[4][2];
            #pragma unroll
            for (int bj = 0; bj < 2; bj++)
                ldsm4(b[2 * bj][0], b[2 * bj][1], b[2 * bj + 1][0], b[2 * bj + 1][1],
                      bLane + kOff + bj * (16 * GP * 2));
            #pragma unroll
            for (int mi = 0; mi < 4; mi++)
                #pragma unroll
                for (int ni = 0; ni < 4; ni++)
                    mma16816(c[mi][ni], a[mi], b[ni]);
        }

        // epilogue: permuted layout -> 4 consecutive logical cols per thread
        #pragma unroll
        for (int tp = 0; tp < 2; tp++) {          // ni pairs (0,1) and (2,3)
            int col = t * 128 + cq + 16 * tp;     // logical, 16B aligned
            float4 bc4 = *(const float4*)(g_bc + col);
            #pragma unroll
            for (int mi = 0; mi < 4; mi++) {
                int row = mg + mi * 16;
                float4 v0, v1;
                v0.x = c[mi][2 * tp][0] + bc4.x;
                v0.y = c[mi][2 * tp][1] + bc4.y;
                v0.z = c[mi][2 * tp + 1][0] + bc4.z;
                v0.w = c[mi][2 * tp + 1][1] + bc4.w;
                v1.x = c[mi][2 * tp][2] + bc4.x;
                v1.y = c[mi][2 * tp][3] + bc4.y;
                v1.z = c[mi][2 * tp + 1][2] + bc4.z;
                v1.w = c[mi][2 * tp + 1][3] + bc4.w;
                __stcs((float4*)(out + (size_t)row * OUT_DIM + col), v0);
                __stcs((float4*)(out + (size_t)(row + 8) * OUT_DIM + col), v1);
            }
        }

        if (t == 5) break;
        __syncthreads();                 // all warps done reading buf t&1
        if (t < 4) {
            cp_tile128((t & 1) ? bB1 : bB0, g_Bf + (size_t)(t + 2) * 128 * E_DIM, tid);
            cp_commit();
            cp_wait<1>();                // B_{t+1} group complete
        } else {
            cp_wait<0>();                // drain B5
        }
        __syncthreads();
    }
}

// ---------------- launch -----------------------------------------------------
extern "C" void kernel_launch(void* const* d_in, const int* in_sizes, int n_in,
                              void* d_out, int out_size)
{
    const int*   device_ids = (const int*)d_in[0];
    const int*   pseudo_ids = (const int*)d_in[1];
    const int*   attr_ids   = (const int*)d_in[2];
    const int*   unit_ids   = (const int*)d_in[3];
    const float* values     = (const float*)d_in[4];
    const int*   mask       = (const int*)d_in[5];
    const float* dev_table  = (const float*)d_in[6];
    const float* pse_table  = (const float*)d_in[7];
    const float* attr_table = (const float*)d_in[8];
    const float* unit_table = (const float*)d_in[9];
    const float* val_w      = (const float*)d_in[10];
    const float* val_b      = (const float*)d_in[11];
    const float* in_proj_w  = (const float*)d_in[12];
    const float* in_proj_b  = (const float*)d_in[13];
    const float* out_proj_w = (const float*)d_in[14];
    const float* out_proj_b = (const float*)d_in[15];
    const float* out_w      = (const float*)d_in[16];
    const float* out_b      = (const float*)d_in[17];
    float* out = (float*)d_out;

    precompute_qkv_kernel<<<143, 384>>>(dev_table, pse_table, attr_table, unit_table,
                                        val_w, val_b, in_proj_w, in_proj_b);
    precompute_wc_kernel<<<768, 128>>>(out_w, out_proj_w, out_proj_b, out_b);
    precompute_tables_kernel<<<NROWS, 128>>>();

    attn_kernel<<<N_TOT / 4, 128>>>(device_ids, pseudo_ids, attr_ids, unit_ids,
                                    values, mask);

    cudaFuncSetAttribute(gemm_mma_kernel, cudaFuncAttributeMaxDynamicSharedMemorySize,
                         G_SMEM_BYTES);
    gemm_mma_kernel<<<N_TOT / 128, 256, G_SMEM_BYTES>>>(out);
}